// round 17
// baseline (speedup 1.0000x reference)
#include <cuda_runtime.h>
#include <cuda_bf16.h>

// Problem constants (SpectralClassifier: B=1024, S=128, D=768)
#define BB 1024
#define SS 128
#define DD 768
#define H1 256
#define H2 64
#define OUTC 2
#define ROWS 8
#define NCHK 4            // d-chunks
#define KCHK (DD / NCHK)  // 192 floats per chunk
#define C4CHK (KCHK / 4)  // 48 float4 per row per chunk
#define PROD_T 256        // producer threads (8 warps)
#define CONS_T 768        // consumer threads (24 warps) = 6 kgroups x 128 colpairs
#define CKG 6             // consumer kgroups

// packed dual-fp32 FMA (sm_100+)
#define FMA_F32X2(d, a, b, c) \
    asm("fma.rn.f32x2 %0, %1, %2, %3;" : "=l"(d) : "l"(a), "l"(b), "l"(c))

__device__ __forceinline__ void cpasync16(float* smem_dst, const float* gsrc) {
    unsigned saddr = (unsigned)__cvta_generic_to_shared(smem_dst);
    asm volatile("cp.async.cg.shared.global [%0], [%1], 16;" :: "r"(saddr), "l"(gsrc) : "memory");
}
#define CP_COMMIT()  asm volatile("cp.async.commit_group;" ::: "memory")
#define CP_WAIT(n)   asm volatile("cp.async.wait_group %0;" :: "n"(n) : "memory")

__device__ __forceinline__ bool mask_at(const void* mask, int idx, int mode) {
    if (mode == 0) return ((const int*)mask)[idx] != 0;
    if (mode == 1) return ((const float*)mask)[idx] != 0.0f;
    return ((const unsigned char*)mask)[idx] != 0;
}

// one k-step: w2v = float2 weights for 2 cols; vkp -> vs[k][0] (8 rows)
#define KSTEP2(w2v, vkp) do {                                             \
    unsigned long long w0, w1;                                            \
    asm("mov.b64 %0, {%1, %1};" : "=l"(w0) : "f"((w2v).x));               \
    asm("mov.b64 %0, {%1, %1};" : "=l"(w1) : "f"((w2v).y));               \
    const ulonglong2 va = *(const ulonglong2*)(vkp);                      \
    const ulonglong2 vb = *(const ulonglong2*)((vkp) + 4);                \
    FMA_F32X2(accp[0], va.x, w0, accp[0]);                                \
    FMA_F32X2(accp[1], va.y, w0, accp[1]);                                \
    FMA_F32X2(accp[2], vb.x, w0, accp[2]);                                \
    FMA_F32X2(accp[3], vb.y, w0, accp[3]);                                \
    FMA_F32X2(accp[4], va.x, w1, accp[4]);                                \
    FMA_F32X2(accp[5], va.y, w1, accp[5]);                                \
    FMA_F32X2(accp[6], vb.x, w1, accp[6]);                                \
    FMA_F32X2(accp[7], vb.y, w1, accp[7]);                                \
} while (0)

// Dynamic smem layout (float words):
//   buf[2][KCHK*ROWS]   : 0     .. 3072   (ping-pong v chunks, [k][r])
//   h1p[CKG][ROWS*H1]   : 3072  .. 15360
//   h1s[ROWS*H1]        : 15360 .. 17408
//   sW2[H1*H2]          : 17408 .. 33792
//   h2s[ROWS*H2]        : 33792 .. 34304
//   s_idx[8][128] (int) : 34304 .. 35328
//   ctrl[12]      (int) : 35328 .. 35340   [0..7]=cnt, 8=badi, 9=badf
#define OFF_BUF   0
#define OFF_H1P   3072
#define OFF_H1S   15360
#define OFF_W2    17408
#define OFF_H2S   33792
#define OFF_IDX   34304
#define OFF_CTRL  35328
#define SMEM_FLOATS 35340

// ---------------------------------------------------------------------------
// Producer: masked seq-sum for one d-chunk -> vb ([k][r], scaled by 1/127).
// ---------------------------------------------------------------------------
__device__ __forceinline__ void gather_chunk(
    const float* __restrict__ hidden, float* __restrict__ vb,
    const int* __restrict__ s_idx, const int* __restrict__ ctrl,
    int r0, int ch, int tid)
{
    const float inv127 = 1.0f / 127.0f;
    #pragma unroll
    for (int w = tid; w < ROWS * C4CHK; w += PROD_T) {
        const int row  = w / C4CHK;
        const int col4 = w % C4CHK;
        const int cnt  = ctrl[row];
        const int* idx = s_idx + row * 128;
        const float4* bp = (const float4*)hidden
            + ((size_t)(r0 + row) * SS) * (DD / 4) + ch * C4CHK + col4;

        float4 a0 = make_float4(0.f, 0.f, 0.f, 0.f);
        float4 a1 = make_float4(0.f, 0.f, 0.f, 0.f);
        int i = 0;
        for (; i + 8 <= cnt; i += 8) {
            float4 x0 = __ldcs(bp + idx[i]     * (DD / 4));
            float4 x1 = __ldcs(bp + idx[i + 1] * (DD / 4));
            float4 x2 = __ldcs(bp + idx[i + 2] * (DD / 4));
            float4 x3 = __ldcs(bp + idx[i + 3] * (DD / 4));
            float4 x4 = __ldcs(bp + idx[i + 4] * (DD / 4));
            float4 x5 = __ldcs(bp + idx[i + 5] * (DD / 4));
            float4 x6 = __ldcs(bp + idx[i + 6] * (DD / 4));
            float4 x7 = __ldcs(bp + idx[i + 7] * (DD / 4));
            a0.x += x0.x + x2.x; a0.y += x0.y + x2.y; a0.z += x0.z + x2.z; a0.w += x0.w + x2.w;
            a1.x += x1.x + x3.x; a1.y += x1.y + x3.y; a1.z += x1.z + x3.z; a1.w += x1.w + x3.w;
            a0.x += x4.x + x6.x; a0.y += x4.y + x6.y; a0.z += x4.z + x6.z; a0.w += x4.w + x6.w;
            a1.x += x5.x + x7.x; a1.y += x5.y + x7.y; a1.z += x5.z + x7.z; a1.w += x5.w + x7.w;
        }
        for (; i < cnt; i++) {
            float4 x = __ldcs(bp + idx[i] * (DD / 4));
            a0.x += x.x; a0.y += x.y; a0.z += x.z; a0.w += x.w;
        }
        const int kb = col4 * 4;
        vb[(kb + 0) * ROWS + row] = (a0.x + a1.x) * inv127;
        vb[(kb + 1) * ROWS + row] = (a0.y + a1.y) * inv127;
        vb[(kb + 2) * ROWS + row] = (a0.z + a1.z) * inv127;
        vb[(kb + 3) * ROWS + row] = (a0.w + a1.w) * inv127;
    }
}

// ---------------------------------------------------------------------------
// Consumer: GEMM1 over one chunk (32 k-steps), accumulators persistent.
// ---------------------------------------------------------------------------
__device__ __forceinline__ void gemm_chunk(
    const float2* __restrict__ wp, const float* __restrict__ vg,
    unsigned long long* accp)
{
    #pragma unroll
    for (int bb = 0; bb < 4; bb++) {
        float2 wA[8];
        #pragma unroll
        for (int u = 0; u < 8; u++)
            wA[u] = __ldg(wp + (bb * 8 + u) * (H1 / 2));
        #pragma unroll
        for (int u = 0; u < 8; u++)
            KSTEP2(wA[u], vg + (bb * 8 + u) * ROWS);
    }
}

// ---------------------------------------------------------------------------
// Fused kernel: masked reduce (producers) pipelined with MLP (consumers).
// Grid 128 x 1024 threads. Warps 0-7 produce, warps 8-31 consume.
// ---------------------------------------------------------------------------
__global__ void __launch_bounds__(1024, 1) fused_kernel(
    const float* __restrict__ hidden, const void* __restrict__ mask,
    const float* __restrict__ W1, const float* __restrict__ b1,
    const float* __restrict__ W2, const float* __restrict__ b2,
    const float* __restrict__ W3, const float* __restrict__ b3,
    float* __restrict__ out)
{
    extern __shared__ float smf[];
    float* buf = smf + OFF_BUF;
    float* h1p = smf + OFF_H1P;
    float* h1s = smf + OFF_H1S;
    float* sW2 = smf + OFF_W2;
    float* h2s = smf + OFF_H2S;
    int* s_idx = (int*)(smf + OFF_IDX);
    int* ctrl  = (int*)(smf + OFF_CTRL);

    const int tid  = threadIdx.x;
    const int wid  = tid >> 5;
    const int lane = tid & 31;
    const int r0   = blockIdx.x * ROWS;

    // --- stage W2 via cp.async (consumed only in GEMM2) ---
    #pragma unroll
    for (int i = tid; i < H1 * H2 / 4; i += 1024)
        cpasync16(&sW2[i * 4], &W2[i * 4]);
    CP_COMMIT();

    // --- mask dtype detection on a 256-word sample ---
    if (tid == 0) { ctrl[8] = 0; ctrl[9] = 0; }
    __syncthreads();
    if (tid < 64) {
        uint4 v = __ldg(&((const uint4*)mask)[tid]);
        unsigned arr[4] = {v.x, v.y, v.z, v.w};
        int bi = 0, bf = 0;
        #pragma unroll
        for (int j = 0; j < 4; j++) {
            unsigned u = arr[j];
            if (u > 1u) bi = 1;
            float f = __uint_as_float(u);
            if (!(f == 0.0f || f == 1.0f)) bf = 1;
        }
        if (bi) atomicOr(&ctrl[8], 1);
        if (bf) atomicOr(&ctrl[9], 1);
    }
    __syncthreads();
    const int mode = (ctrl[8] == 0) ? 0 : ((ctrl[9] == 0) ? 1 : 2);

    // --- mask compaction: warp r compacts row r (4 passes of 32) ---
    if (wid < ROWS) {
        const int r = wid;
        int base = 0;
        #pragma unroll
        for (int p = 0; p < 4; p++) {
            int s = p * 32 + lane;
            bool m = (s >= 1) && mask_at(mask, (r0 + r) * SS + s, mode);
            unsigned bal = __ballot_sync(0xffffffffu, m);
            if (m) s_idx[r * 128 + base + __popc(bal & ((1u << lane) - 1u))] = s;
            base += __popc(bal);
        }
        if (lane == 0) ctrl[r] = base;
    }
    __syncthreads();

    // --- pipeline: producers gather ch+1 while consumers GEMM ch ---
    unsigned long long accp[8];
    #pragma unroll
    for (int j = 0; j < 8; j++) accp[j] = 0ull;

    const int ct = tid - PROD_T;          // consumer index 0..767
    const int c  = ct & 127;              // col pair: cols 2c, 2c+1
    const int kg = ct >> 7;               // 0..5

    if (tid < PROD_T)
        gather_chunk(hidden, &buf[0], s_idx, ctrl, r0, 0, tid);
    __syncthreads();

    #pragma unroll 1
    for (int ch = 0; ch < NCHK; ch++) {
        if (tid < PROD_T) {
            if (ch + 1 < NCHK)
                gather_chunk(hidden, &buf[((ch + 1) & 1) * KCHK * ROWS],
                             s_idx, ctrl, r0, ch + 1, tid);
        } else {
            const float2* wp = (const float2*)W1
                + (size_t)(ch * KCHK + kg * 32) * (H1 / 2) + c;
            const float* vg = &buf[(ch & 1) * KCHK * ROWS + (kg * 32) * ROWS];
            gemm_chunk(wp, vg, accp);
        }
        __syncthreads();
    }

    // --- consumers write 6 kgroup partials: h1p[kg][row*256 + 2c + {0,1}] ---
    if (tid >= PROD_T) {
        float* hp = h1p + kg * (ROWS * H1);
        #pragma unroll
        for (int j = 0; j < 4; j++) {
            float lo0, hi0, lo1, hi1;
            asm("mov.b64 {%0, %1}, %2;" : "=f"(lo0), "=f"(hi0) : "l"(accp[j]));
            asm("mov.b64 {%0, %1}, %2;" : "=f"(lo1), "=f"(hi1) : "l"(accp[4 + j]));
            *(float2*)&hp[(2 * j) * H1 + 2 * c]     = make_float2(lo0, lo1);
            *(float2*)&hp[(2 * j + 1) * H1 + 2 * c] = make_float2(hi0, hi1);
        }
    }
    __syncthreads();

    // --- reduce 6 partials -> h1s (bias + relu). 1024 threads x 2 floats ---
    {
        const int idx = tid * 2;           // 0..2046
        const int col = idx & (H1 - 1);
        float2 s = *(const float2*)&h1p[idx];
        #pragma unroll
        for (int g = 1; g < CKG; g++) {
            float2 p = *(const float2*)&h1p[g * (ROWS * H1) + idx];
            s.x += p.x; s.y += p.y;
        }
        float2 bb = *(const float2*)&b1[col];
        s.x = fmaxf(s.x + bb.x, 0.0f);
        s.y = fmaxf(s.y + bb.y, 0.0f);
        *(float2*)&h1s[idx] = s;
    }
    CP_WAIT(0);
    __syncthreads();

    // --- GEMM2 (smem): threads 0..511 -> (r = t>>6, j = t&63) ---
    if (tid < 512) {
        const int j = tid & (H2 - 1);
        const int r = tid >> 6;            // 0..7
        float s0 = 0.0f;
        #pragma unroll 16
        for (int k = 0; k < H1; k++)
            s0 = fmaf(h1s[r * H1 + k], sW2[k * H2 + j], s0);
        h2s[r * H2 + j] = fmaxf(s0 + __ldg(&b2[j]), 0.0f);
    }
    __syncthreads();

    // --- GEMM3: 16 outputs (8 rows x 2 logits) ---
    if (tid < ROWS * OUTC) {
        const int r = tid >> 1;
        const int j = tid & 1;
        float s = __ldg(&b3[j]);
        #pragma unroll 8
        for (int cc = 0; cc < H2; cc++)
            s = fmaf(h2s[r * H2 + cc], __ldg(&W3[cc * OUTC + j]), s);
        out[(size_t)(r0 + r) * OUTC + j] = s;
    }
}

// ---------------------------------------------------------------------------
extern "C" void kernel_launch(void* const* d_in, const int* in_sizes, int n_in,
                              void* d_out, int out_size) {
    const float* hidden = (const float*)d_in[0];
    const void*  mask   = d_in[1];
    const float* W1 = (const float*)d_in[2];
    const float* b1 = (const float*)d_in[3];
    const float* W2 = (const float*)d_in[4];
    const float* b2 = (const float*)d_in[5];
    const float* W3 = (const float*)d_in[6];
    const float* b3 = (const float*)d_in[7];
    float* out = (float*)d_out;

    static int smem_set = 0;
    if (!smem_set) {
        cudaFuncSetAttribute(fused_kernel,
                             cudaFuncAttributeMaxDynamicSharedMemorySize,
                             SMEM_FLOATS * sizeof(float));
        smem_set = 1;
    }

    fused_kernel<<<BB / ROWS, 1024, SMEM_FLOATS * sizeof(float)>>>(
        hidden, mask, W1, b1, W2, b2, W3, b3, out);
}